// round 2
// baseline (speedup 1.0000x reference)
#include <cuda_runtime.h>

#define NN 10000
#define EE 320000

__device__ float g_b0[(size_t)NN*1024*64];
__device__ float g_b1[(size_t)NN*256*64];
__device__ float g_cf[NN*64];
__device__ float g_nA[NN*64];
__device__ float g_nB[NN*64];
__device__ float g_agg[NN*64];
__device__ float g_edge[(size_t)EE*64];

// ---------------------------------------------------------------- conv0: 3->64
__global__ void __launch_bounds__(256) k_conv0(const float* __restrict__ crop,
    const float* __restrict__ w0, const float* __restrict__ b0, float* __restrict__ out) {
    __shared__ float Ws[12*64], Bs[64], As[64][13];
    int t = threadIdx.x;
    size_t Rbase = (size_t)blockIdx.x * 64;
    for (int i = t; i < 768; i += 256) {
        int oc = i / 12, r = i - oc * 12;            // r = c*4 + (ky*2+kx)
        Ws[r * 64 + oc] = w0[i];
    }
    if (t < 64) Bs[t] = b0[t];
    for (int e = t; e < 768; e += 256) {
        int row = e / 12, k = e - row * 12, c = k >> 2, p = k & 3;
        size_t R = Rbase + row;
        int n = (int)(R >> 10), sp = (int)(R & 1023), oy = sp >> 5, ox = sp & 31;
        int y = 2 * oy + (p >> 1), x = 2 * ox + (p & 1);
        As[row][k] = crop[(((size_t)n * 3 + c) * 64 + y) * 64 + x];
    }
    __syncthreads();
    int tr = t >> 4, tc = t & 15;
    float acc[4][4];
    float4 b4 = *(const float4*)&Bs[tc * 4];
    #pragma unroll
    for (int i = 0; i < 4; i++) { acc[i][0]=b4.x; acc[i][1]=b4.y; acc[i][2]=b4.z; acc[i][3]=b4.w; }
    #pragma unroll
    for (int k = 0; k < 12; k++) {
        float4 w = *(const float4*)&Ws[k * 64 + tc * 4];
        #pragma unroll
        for (int i = 0; i < 4; i++) {
            float a = As[tr * 4 + i][k];
            acc[i][0] += a*w.x; acc[i][1] += a*w.y; acc[i][2] += a*w.z; acc[i][3] += a*w.w;
        }
    }
    #pragma unroll
    for (int i = 0; i < 4; i++) {
        float4 r; r.x=fmaxf(acc[i][0],0.f); r.y=fmaxf(acc[i][1],0.f);
        r.z=fmaxf(acc[i][2],0.f); r.w=fmaxf(acc[i][3],0.f);
        *(float4*)&out[(Rbase + tr * 4 + i) * 64 + tc * 4] = r;
    }
}

// ------------------------------------------------- generic conv 64->64, k2 s2
__global__ void __launch_bounds__(256) k_conv(const float* __restrict__ in,
    float* __restrict__ out, const float* __restrict__ w, const float* __restrict__ b,
    int so_bits, int M) {
    extern __shared__ float sm[];
    float* Ws = sm;            // 16384
    float* Bs = Ws + 16384;    // 64
    float* As = Bs + 64;       // 64*68
    int t = threadIdx.x;
    int Rbase = blockIdx.x * 64;
    for (int i = t; i < 16384; i += 256) {
        int oc = i >> 8, r = i & 255, ic = r >> 2, p = r & 3;
        Ws[(p * 64 + ic) * 64 + oc] = w[i];
    }
    if (t < 64) Bs[t] = b[t];
    int S_out = 1 << so_bits, S_in = S_out * 2, so2 = 2 * so_bits;
    int tr = t >> 4, tc = t & 15;
    float acc[4][4];
    for (int p = 0; p < 4; p++) {
        __syncthreads();
        int ky = p >> 1, kx = p & 1;
        for (int e = t * 4; e < 4096; e += 1024) {
            int row = e >> 6, c4 = e & 63;
            int R = Rbase + row;
            float4 v = make_float4(0.f, 0.f, 0.f, 0.f);
            if (R < M) {
                int n = R >> so2, sp = R & (S_out * S_out - 1);
                int oy = sp >> so_bits, ox = sp & (S_out - 1);
                int y = 2 * oy + ky, x = 2 * ox + kx;
                v = *(const float4*)&in[(((size_t)n * S_in + y) * S_in + x) * 64 + c4];
            }
            *(float4*)&As[row * 68 + c4] = v;
        }
        __syncthreads();
        if (p == 0) {
            float4 b4 = *(const float4*)&Bs[tc * 4];
            #pragma unroll
            for (int i = 0; i < 4; i++) { acc[i][0]=b4.x; acc[i][1]=b4.y; acc[i][2]=b4.z; acc[i][3]=b4.w; }
        }
        for (int k = 0; k < 64; k++) {
            float4 w4 = *(const float4*)&Ws[(p * 64 + k) * 64 + tc * 4];
            #pragma unroll
            for (int i = 0; i < 4; i++) {
                float a = As[(tr * 4 + i) * 68 + k];
                acc[i][0] += a*w4.x; acc[i][1] += a*w4.y; acc[i][2] += a*w4.z; acc[i][3] += a*w4.w;
            }
        }
    }
    #pragma unroll
    for (int i = 0; i < 4; i++) {
        int R = Rbase + tr * 4 + i;
        if (R < M) {
            float4 r; r.x=fmaxf(acc[i][0],0.f); r.y=fmaxf(acc[i][1],0.f);
            r.z=fmaxf(acc[i][2],0.f); r.w=fmaxf(acc[i][3],0.f);
            *(float4*)&out[(size_t)R * 64 + tc * 4] = r;
        }
    }
}

// --------------------------------------------- node_update: [x|cf]@W + LN
__global__ void __launch_bounds__(256) k_nodeup(const float* __restrict__ x,
    const float* __restrict__ cf, const float* __restrict__ w, const float* __restrict__ b,
    const float* __restrict__ g, const float* __restrict__ be, float* __restrict__ out) {
    extern __shared__ float sm[];
    float* Ws = sm;           // 6144
    float* Bs = Ws + 6144; float* Gs = Bs + 64; float* BEs = Gs + 64;
    float* mu = BEs + 64; float* rs = mu + 64;
    float* As = rs + 64;      // 64*100
    float* Hs = As + 6400;    // 64*68
    int t = threadIdx.x;
    int Rbase = blockIdx.x * 64;
    for (int i = t; i < 6144; i += 256) Ws[i] = w[i];
    if (t < 64) { Bs[t]=b[t]; Gs[t]=g[t]; BEs[t]=be[t]; }
    for (int e = t; e < 2048; e += 256) {
        int row = e >> 5, c = e & 31, nd = Rbase + row;
        As[row * 100 + c] = (nd < NN) ? x[nd * 32 + c] : 0.f;
    }
    for (int e = t; e < 4096; e += 256) {
        int row = e >> 6, c = e & 63, nd = Rbase + row;
        As[row * 100 + 32 + c] = (nd < NN) ? cf[nd * 64 + c] : 0.f;
    }
    __syncthreads();
    int tr = t >> 4, tc = t & 15;
    float acc[4][4];
    float4 b4 = *(const float4*)&Bs[tc * 4];
    #pragma unroll
    for (int i = 0; i < 4; i++) { acc[i][0]=b4.x; acc[i][1]=b4.y; acc[i][2]=b4.z; acc[i][3]=b4.w; }
    for (int k = 0; k < 96; k++) {
        float4 w4 = *(const float4*)&Ws[k * 64 + tc * 4];
        #pragma unroll
        for (int i = 0; i < 4; i++) {
            float a = As[(tr * 4 + i) * 100 + k];
            acc[i][0] += a*w4.x; acc[i][1] += a*w4.y; acc[i][2] += a*w4.z; acc[i][3] += a*w4.w;
        }
    }
    #pragma unroll
    for (int i = 0; i < 4; i++) {
        float4 r; r.x=fmaxf(acc[i][0],0.f); r.y=fmaxf(acc[i][1],0.f);
        r.z=fmaxf(acc[i][2],0.f); r.w=fmaxf(acc[i][3],0.f);
        *(float4*)&Hs[(tr * 4 + i) * 68 + tc * 4] = r;
    }
    __syncthreads();
    if (t < 64) {
        float s = 0.f, sq = 0.f;
        for (int c = 0; c < 64; c++) { float v = Hs[t * 68 + c]; s += v; sq += v * v; }
        float m = s * (1.f / 64.f);
        mu[t] = m; rs[t] = rsqrtf(sq * (1.f / 64.f) - m * m + 1e-5f);
    }
    __syncthreads();
    for (int i = t; i < 4096; i += 256) {
        int r = i >> 6, c = i & 63, nd = Rbase + r;
        if (nd < NN) out[nd * 64 + c] = (Hs[r * 68 + c] - mu[r]) * rs[r] * Gs[c] + BEs[c];
    }
}

// --------------------------------------------- edge_update: ea@W + LN
__global__ void __launch_bounds__(256) k_edgeup(const float* __restrict__ ea,
    const float* __restrict__ w, const float* __restrict__ b,
    const float* __restrict__ g, const float* __restrict__ be, float* __restrict__ out) {
    __shared__ float Ws[384], Bs[64], Gs[64], BEs[64], Aa[64][8], Hs[64][68], mu[64], rs[64];
    int t = threadIdx.x;
    int ebase = blockIdx.x * 64;
    for (int i = t; i < 384; i += 256) Ws[i] = w[i];
    if (t < 64) { Bs[t]=b[t]; Gs[t]=g[t]; BEs[t]=be[t]; }
    for (int e = t; e < 384; e += 256) {
        int row = e / 6, k = e - row * 6;
        Aa[row][k] = ea[(size_t)(ebase + row) * 6 + k];
    }
    __syncthreads();
    int r = t >> 2, cg = (t & 3) * 16;
    float a0=Aa[r][0],a1=Aa[r][1],a2=Aa[r][2],a3=Aa[r][3],a4=Aa[r][4],a5=Aa[r][5];
    #pragma unroll
    for (int j = 0; j < 16; j++) {
        int c = cg + j;
        float h = Bs[c] + a0*Ws[c] + a1*Ws[64+c] + a2*Ws[128+c] + a3*Ws[192+c] + a4*Ws[256+c] + a5*Ws[320+c];
        Hs[r][c] = fmaxf(h, 0.f);
    }
    __syncthreads();
    if (t < 64) {
        float s = 0.f, sq = 0.f;
        for (int c = 0; c < 64; c++) { float v = Hs[t][c]; s += v; sq += v * v; }
        float m = s * (1.f / 64.f);
        mu[t] = m; rs[t] = rsqrtf(sq * (1.f / 64.f) - m * m + 1e-5f);
    }
    __syncthreads();
    for (int i = t; i < 4096; i += 256) {
        int rr = i >> 6, c = i & 63;
        out[(size_t)ebase * 64 + i] = (Hs[rr][c] - mu[rr]) * rs[rr] * Gs[c] + BEs[c];
    }
}

// --------------------------- edge message MLP + fused scatter-add (segment sum)
__global__ void __launch_bounds__(256) k_msg(const float* __restrict__ node,
    const float* __restrict__ edge, const int* __restrict__ ei,
    const float* __restrict__ w1, const float* __restrict__ b1,
    const float* __restrict__ w2, const float* __restrict__ b2, float* __restrict__ agg) {
    extern __shared__ float sm[];
    float* W1s = sm;           // 12288
    float* W2s = W1s + 12288;  // 4096
    float* B1s = W2s + 4096; float* B2s = B1s + 64;
    float* As = B2s + 64;      // 64*68
    float* Hs = As + 4352;     // 64*68
    int* dsts = (int*)(Hs + 4352);
    int* srcs = dsts + 64;
    int t = threadIdx.x;
    int ebase = blockIdx.x * 64;
    for (int i = t; i < 12288; i += 256) W1s[i] = w1[i];
    for (int i = t; i < 4096; i += 256) W2s[i] = w2[i];
    if (t < 64) { B1s[t]=b1[t]; B2s[t]=b2[t]; srcs[t]=ei[ebase+t]; dsts[t]=ei[EE+ebase+t]; }
    int tr = t >> 4, tc = t & 15;
    float acc[4][4];
    for (int ch = 0; ch < 3; ch++) {
        __syncthreads();
        for (int e = t * 4; e < 4096; e += 1024) {
            int row = e >> 6, c4 = e & 63;
            const float* base = (ch == 0) ? &node[(size_t)dsts[row] * 64]
                              : (ch == 1) ? &node[(size_t)srcs[row] * 64]
                                          : &edge[(size_t)(ebase + row) * 64];
            *(float4*)&As[row * 68 + c4] = *(const float4*)&base[c4];
        }
        __syncthreads();
        if (ch == 0) {
            float4 b4 = *(const float4*)&B1s[tc * 4];
            #pragma unroll
            for (int i = 0; i < 4; i++) { acc[i][0]=b4.x; acc[i][1]=b4.y; acc[i][2]=b4.z; acc[i][3]=b4.w; }
        }
        for (int k = 0; k < 64; k++) {
            float4 w4 = *(const float4*)&W1s[(ch * 64 + k) * 64 + tc * 4];
            #pragma unroll
            for (int i = 0; i < 4; i++) {
                float a = As[(tr * 4 + i) * 68 + k];
                acc[i][0] += a*w4.x; acc[i][1] += a*w4.y; acc[i][2] += a*w4.z; acc[i][3] += a*w4.w;
            }
        }
    }
    #pragma unroll
    for (int i = 0; i < 4; i++) {
        float4 r; r.x=fmaxf(acc[i][0],0.f); r.y=fmaxf(acc[i][1],0.f);
        r.z=fmaxf(acc[i][2],0.f); r.w=fmaxf(acc[i][3],0.f);
        *(float4*)&Hs[(tr * 4 + i) * 68 + tc * 4] = r;
    }
    __syncthreads();
    float a2[4][4];
    {
        float4 b4 = *(const float4*)&B2s[tc * 4];
        #pragma unroll
        for (int i = 0; i < 4; i++) { a2[i][0]=b4.x; a2[i][1]=b4.y; a2[i][2]=b4.z; a2[i][3]=b4.w; }
    }
    for (int k = 0; k < 64; k++) {
        float4 w4 = *(const float4*)&W2s[k * 64 + tc * 4];
        #pragma unroll
        for (int i = 0; i < 4; i++) {
            float a = Hs[(tr * 4 + i) * 68 + k];
            a2[i][0] += a*w4.x; a2[i][1] += a*w4.y; a2[i][2] += a*w4.z; a2[i][3] += a*w4.w;
        }
    }
    #pragma unroll
    for (int i = 0; i < 4; i++) {
        int d = dsts[tr * 4 + i];
        #pragma unroll
        for (int j = 0; j < 4; j++)
            atomicAdd(&agg[(size_t)d * 64 + tc * 4 + j], a2[i][j]);
    }
}

// --------------------------------------------- node MLP: [node|agg] 2-layer
__global__ void __launch_bounds__(256) k_nodemlp(const float* __restrict__ node,
    const float* __restrict__ agg, const float* __restrict__ w1, const float* __restrict__ b1,
    const float* __restrict__ w2, const float* __restrict__ b2, float* __restrict__ out) {
    extern __shared__ float sm[];
    float* W1s = sm;           // 8192
    float* W2s = W1s + 8192;   // 4096
    float* B1s = W2s + 4096; float* B2s = B1s + 64;
    float* As = B2s + 64;      // 64*68
    float* Hs = As + 4352;     // 64*68
    int t = threadIdx.x;
    int Rbase = blockIdx.x * 64;
    for (int i = t; i < 8192; i += 256) W1s[i] = w1[i];
    for (int i = t; i < 4096; i += 256) W2s[i] = w2[i];
    if (t < 64) { B1s[t]=b1[t]; B2s[t]=b2[t]; }
    int tr = t >> 4, tc = t & 15;
    float acc[4][4];
    for (int ch = 0; ch < 2; ch++) {
        __syncthreads();
        for (int e = t * 4; e < 4096; e += 1024) {
            int row = e >> 6, c4 = e & 63, nd = Rbase + row;
            float4 v = make_float4(0.f,0.f,0.f,0.f);
            if (nd < NN) {
                const float* base = (ch == 0) ? &node[(size_t)nd * 64] : &agg[(size_t)nd * 64];
                v = *(const float4*)&base[c4];
            }
            *(float4*)&As[row * 68 + c4] = v;
        }
        __syncthreads();
        if (ch == 0) {
            float4 b4 = *(const float4*)&B1s[tc * 4];
            #pragma unroll
            for (int i = 0; i < 4; i++) { acc[i][0]=b4.x; acc[i][1]=b4.y; acc[i][2]=b4.z; acc[i][3]=b4.w; }
        }
        for (int k = 0; k < 64; k++) {
            float4 w4 = *(const float4*)&W1s[(ch * 64 + k) * 64 + tc * 4];
            #pragma unroll
            for (int i = 0; i < 4; i++) {
                float a = As[(tr * 4 + i) * 68 + k];
                acc[i][0] += a*w4.x; acc[i][1] += a*w4.y; acc[i][2] += a*w4.z; acc[i][3] += a*w4.w;
            }
        }
    }
    #pragma unroll
    for (int i = 0; i < 4; i++) {
        float4 r; r.x=fmaxf(acc[i][0],0.f); r.y=fmaxf(acc[i][1],0.f);
        r.z=fmaxf(acc[i][2],0.f); r.w=fmaxf(acc[i][3],0.f);
        *(float4*)&Hs[(tr * 4 + i) * 68 + tc * 4] = r;
    }
    __syncthreads();
    float a2[4][4];
    {
        float4 b4 = *(const float4*)&B2s[tc * 4];
        #pragma unroll
        for (int i = 0; i < 4; i++) { a2[i][0]=b4.x; a2[i][1]=b4.y; a2[i][2]=b4.z; a2[i][3]=b4.w; }
    }
    for (int k = 0; k < 64; k++) {
        float4 w4 = *(const float4*)&W2s[k * 64 + tc * 4];
        #pragma unroll
        for (int i = 0; i < 4; i++) {
            float a = Hs[(tr * 4 + i) * 68 + k];
            a2[i][0] += a*w4.x; a2[i][1] += a*w4.y; a2[i][2] += a*w4.z; a2[i][3] += a*w4.w;
        }
    }
    #pragma unroll
    for (int i = 0; i < 4; i++) {
        int nd = Rbase + tr * 4 + i;
        if (nd < NN) {
            float4 r; r.x=a2[i][0]; r.y=a2[i][1]; r.z=a2[i][2]; r.w=a2[i][3];
            *(float4*)&out[(size_t)nd * 64 + tc * 4] = r;
        }
    }
}

// --------------------------------------------- final edge MLP: 134->128->64->1
__global__ void __launch_bounds__(256) k_final(const float* __restrict__ node,
    const float* __restrict__ ea, const int* __restrict__ ei,
    const float* __restrict__ w1, const float* __restrict__ b1,
    const float* __restrict__ w2, const float* __restrict__ b2,
    const float* __restrict__ w3, const float* __restrict__ b3, float* __restrict__ out) {
    extern __shared__ float sm[];
    float* W1s = sm;              // 17152
    float* B1s = W1s + 17152;     // 128
    float* W2s = B1s + 128;       // 8192
    float* B2s = W2s + 8192;      // 64
    float* w3s = B2s + 64;        // 64
    float* b3s = w3s + 64;        // 4 (padded)
    float* As  = b3s + 4;         // 64*68
    float* Hs  = As + 4352;       // 64*132
    float* H2s = Hs + 8448;       // 64*68
    int* srcs = (int*)(H2s + 4352);
    int* dsts = srcs + 64;
    int t = threadIdx.x;
    int ebase = blockIdx.x * 64;
    for (int i = t; i < 17152; i += 256) W1s[i] = w1[i];
    for (int i = t; i < 8192; i += 256) W2s[i] = w2[i];
    if (t < 128) B1s[t] = b1[t];
    if (t < 64) { B2s[t]=b2[t]; w3s[t]=w3[t]; srcs[t]=ei[ebase+t]; dsts[t]=ei[EE+ebase+t]; }
    if (t == 0) b3s[0] = b3[0];
    int tr = t >> 4, tc = t & 15;
    float acc[4][8];
    for (int ch = 0; ch < 2; ch++) {
        __syncthreads();
        for (int e = t * 4; e < 4096; e += 1024) {
            int row = e >> 6, c4 = e & 63;
            const float* base = (ch == 0) ? &node[(size_t)srcs[row] * 64]
                                          : &node[(size_t)dsts[row] * 64];
            *(float4*)&As[row * 68 + c4] = *(const float4*)&base[c4];
        }
        __syncthreads();
        if (ch == 0) {
            #pragma unroll
            for (int i = 0; i < 4; i++)
                #pragma unroll
                for (int j = 0; j < 8; j++) acc[i][j] = B1s[tc * 8 + j];
        }
        for (int k = 0; k < 64; k++) {
            float4 wa = *(const float4*)&W1s[(ch * 64 + k) * 128 + tc * 8];
            float4 wb = *(const float4*)&W1s[(ch * 64 + k) * 128 + tc * 8 + 4];
            #pragma unroll
            for (int i = 0; i < 4; i++) {
                float a = As[(tr * 4 + i) * 68 + k];
                acc[i][0]+=a*wa.x; acc[i][1]+=a*wa.y; acc[i][2]+=a*wa.z; acc[i][3]+=a*wa.w;
                acc[i][4]+=a*wb.x; acc[i][5]+=a*wb.y; acc[i][6]+=a*wb.z; acc[i][7]+=a*wb.w;
            }
        }
    }
    __syncthreads();
    // edge_attr chunk K=6 (reuse As as [64][8])
    for (int e = t; e < 384; e += 256) {
        int row = e / 6, k = e - row * 6;
        As[row * 8 + k] = ea[(size_t)(ebase + row) * 6 + k];
    }
    __syncthreads();
    for (int k = 0; k < 6; k++) {
        float4 wa = *(const float4*)&W1s[(128 + k) * 128 + tc * 8];
        float4 wb = *(const float4*)&W1s[(128 + k) * 128 + tc * 8 + 4];
        #pragma unroll
        for (int i = 0; i < 4; i++) {
            float a = As[(tr * 4 + i) * 8 + k];
            acc[i][0]+=a*wa.x; acc[i][1]+=a*wa.y; acc[i][2]+=a*wa.z; acc[i][3]+=a*wa.w;
            acc[i][4]+=a*wb.x; acc[i][5]+=a*wb.y; acc[i][6]+=a*wb.z; acc[i][7]+=a*wb.w;
        }
    }
    #pragma unroll
    for (int i = 0; i < 4; i++)
        #pragma unroll
        for (int j = 0; j < 8; j++)
            Hs[(tr * 4 + i) * 132 + tc * 8 + j] = fmaxf(acc[i][j], 0.f);
    __syncthreads();
    float a2[4][4];
    #pragma unroll
    for (int i = 0; i < 4; i++)
        #pragma unroll
        for (int j = 0; j < 4; j++) a2[i][j] = B2s[tc * 4 + j];
    for (int k = 0; k < 128; k++) {
        float4 w4 = *(const float4*)&W2s[k * 64 + tc * 4];
        #pragma unroll
        for (int i = 0; i < 4; i++) {
            float a = Hs[(tr * 4 + i) * 132 + k];
            a2[i][0] += a*w4.x; a2[i][1] += a*w4.y; a2[i][2] += a*w4.z; a2[i][3] += a*w4.w;
        }
    }
    #pragma unroll
    for (int i = 0; i < 4; i++)
        #pragma unroll
        for (int j = 0; j < 4; j++)
            H2s[(tr * 4 + i) * 68 + tc * 4 + j] = fmaxf(a2[i][j], 0.f);
    __syncthreads();
    if (t < 64) {
        float s = b3s[0];
        for (int c = 0; c < 64; c++) s += H2s[t * 68 + c] * w3s[c];
        out[ebase + t] = s;
    }
}

// ============================================================================
extern "C" void kernel_launch(void* const* d_in, const int* in_sizes, int n_in,
                              void* d_out, int out_size) {
    const float *x=0,*ea=0,*crop=0,*cw0=0,*cb0=0,*cw=0,*cb=0,*nu_w=0,*nu_b=0,*nu_g=0,*nu_be=0,
        *eu_w=0,*eu_b=0,*eu_g=0,*eu_be=0,*ie_w1=0,*ie_b1=0,*ie_w2=0,*ie_b2=0,
        *in_w1=0,*in_b1=0,*in_w2=0,*in_b2=0,*em_w1=0,*em_b1=0,*em_w2=0,*em_b2=0,*em_w3=0,*em_b3=0;
    const int* ei = 0;
    int c64 = 0, c256 = 0, c16k = 0;
    for (int i = 0; i < n_in; i++) {
        const float* p = (const float*)d_in[i];
        switch (in_sizes[i]) {
            case 320000: x = p; break;
            case 640000: ei = (const int*)p; break;
            case 1920000: ea = p; break;
            case 122880000: crop = p; break;
            case 768: cw0 = p; break;
            case 81920: cw = p; break;
            case 320: cb = p; break;
            case 6144: nu_w = p; break;
            case 384: eu_w = p; break;
            case 49152: ie_w1 = p; break;
            case 32768: in_w1 = p; break;
            case 17152: em_w1 = p; break;
            case 128: em_b1 = p; break;
            case 8192: em_w2 = p; break;
            case 1: em_b3 = p; break;
            case 16384: if (c16k++ == 0) ie_w2 = p; else in_w2 = p; break;
            case 256:
                if (c256 == 0) ie_b1 = p; else if (c256 == 1) ie_b2 = p;
                else if (c256 == 2) in_b1 = p; else in_b2 = p;
                c256++; break;
            case 64: {
                const float** slots[9] = {&cb0,&nu_b,&nu_g,&nu_be,&eu_b,&eu_g,&eu_be,&em_b2,&em_w3};
                if (c64 < 9) *slots[c64] = p;
                c64++; break;
            }
            default: break;
        }
    }
    float *b0, *b1, *cf, *nA, *nB, *agg, *edg;
    cudaGetSymbolAddress((void**)&b0, g_b0);
    cudaGetSymbolAddress((void**)&b1, g_b1);
    cudaGetSymbolAddress((void**)&cf, g_cf);
    cudaGetSymbolAddress((void**)&nA, g_nA);
    cudaGetSymbolAddress((void**)&nB, g_nB);
    cudaGetSymbolAddress((void**)&agg, g_agg);
    cudaGetSymbolAddress((void**)&edg, g_edge);

    const int SM_CONV = (16384 + 64 + 64 * 68) * 4;
    const int SM_NU   = (6144 + 64*5 + 64*100 + 64*68 + 64) * 4;
    const int SM_MSG  = (12288 + 4096 + 128 + 4352 + 4352) * 4 + 512;
    const int SM_NM   = (8192 + 4096 + 128 + 4352 + 4352) * 4;
    const int SM_FIN  = (17152 + 128 + 8192 + 64 + 64 + 4 + 4352 + 8448 + 4352) * 4 + 512;
    cudaFuncSetAttribute(k_conv,    cudaFuncAttributeMaxDynamicSharedMemorySize, SM_CONV);
    cudaFuncSetAttribute(k_nodeup,  cudaFuncAttributeMaxDynamicSharedMemorySize, SM_NU);
    cudaFuncSetAttribute(k_msg,     cudaFuncAttributeMaxDynamicSharedMemorySize, SM_MSG);
    cudaFuncSetAttribute(k_nodemlp, cudaFuncAttributeMaxDynamicSharedMemorySize, SM_NM);
    cudaFuncSetAttribute(k_final,   cudaFuncAttributeMaxDynamicSharedMemorySize, SM_FIN);

    // CNN stack
    k_conv0<<<160000, 256>>>(crop, cw0, cb0, b0);
    k_conv<<<40000, 256, SM_CONV>>>(b0, b1, cw,           cb,       4, NN * 256);
    k_conv<<<10000, 256, SM_CONV>>>(b1, b0, cw + 16384,   cb + 64,  3, NN * 64);
    k_conv<<<2500,  256, SM_CONV>>>(b0, b1, cw + 32768,   cb + 128, 2, NN * 16);
    k_conv<<<625,   256, SM_CONV>>>(b1, b0, cw + 49152,   cb + 192, 1, NN * 4);
    k_conv<<<157,   256, SM_CONV>>>(b0, cf, cw + 65536,   cb + 256, 0, NN);
    // encoders
    k_nodeup<<<157, 256, SM_NU>>>(x, cf, nu_w, nu_b, nu_g, nu_be, nA);
    k_edgeup<<<5000, 256>>>(ea, eu_w, eu_b, eu_g, eu_be, edg);
    // 4 interaction layers (ping-pong nA <-> nB)
    float* cur = nA; float* nxt = nB;
    for (int l = 0; l < 4; l++) {
        cudaMemsetAsync(agg, 0, (size_t)NN * 64 * sizeof(float), 0);
        k_msg<<<5000, 256, SM_MSG>>>(cur, edg, ei, ie_w1 + l * 12288, ie_b1 + l * 64,
                                     ie_w2 + l * 4096, ie_b2 + l * 64, agg);
        k_nodemlp<<<157, 256, SM_NM>>>(cur, agg, in_w1 + l * 8192, in_b1 + l * 64,
                                       in_w2 + l * 4096, in_b2 + l * 64, nxt);
        float* tmp = cur; cur = nxt; nxt = tmp;
    }
    // final edge MLP
    k_final<<<5000, 256, SM_FIN>>>(cur, ea, ei, em_w1, em_b1, em_w2, em_b2,
                                   em_w3, em_b3, (float*)d_out);
}